// round 8
// baseline (speedup 1.0000x reference)
#include <cuda_runtime.h>
#include <cuda_fp16.h>
#include <stdint.h>
#include <math.h>

#define N_TOK  32768
#define HID    1024
#define NEXP   64
#define H4     256
#define N_TOT  320          // 64 router + 256 hidden

#define MT      128         // M rows per CTA
#define KC      32          // K per chunk
#define NCHUNK  (HID / KC)  // 32
#define THREADS 512

// smem stage layout (bytes): A_HI 8K | A_LO 8K | B_HI 20K | B_LO 20K = 57344
#define A_LO_OFF 8192
#define B_HI_OFF 16384
#define B_LO_OFF 36864
#define ST_BYTES 57344
#define NSTAGE   4
#define SMEM_TOTAL (NSTAGE * ST_BYTES)   // 229376

// ---------------- device scratch ----------------
__device__ __align__(16) __half g_xhi[(size_t)N_TOK * HID];
__device__ __align__(16) __half g_xlo[(size_t)N_TOK * HID];
__device__ __align__(16) __half g_whi[N_TOT * HID];
__device__ __align__(16) __half g_wlo[N_TOT * HID];
__device__ float g_load[NEXP];
__device__ float g_ent;

__device__ __forceinline__ uint32_t smem_u32(const void* p) {
    uint32_t a;
    asm("{ .reg .u64 t; cvta.to.shared.u64 t, %1; cvt.u32.u64 %0, t; }" : "=r"(a) : "l"(p));
    return a;
}
__device__ __forceinline__ void cp16(uint32_t dst, const void* src) {
    asm volatile("cp.async.cg.shared.global [%0], [%1], 16;"
                 :: "r"(dst), "l"(__cvta_generic_to_global(src)));
}
__device__ __forceinline__ void ldsm4(uint32_t* r, uint32_t addr) {
    asm volatile("ldmatrix.sync.aligned.m8n8.x4.shared.b16 {%0,%1,%2,%3}, [%4];"
                 : "=r"(r[0]), "=r"(r[1]), "=r"(r[2]), "=r"(r[3]) : "r"(addr));
}
__device__ __forceinline__ void ldsm2(uint32_t* r, uint32_t addr) {
    asm volatile("ldmatrix.sync.aligned.m8n8.x2.shared.b16 {%0,%1}, [%2];"
                 : "=r"(r[0]), "=r"(r[1]) : "r"(addr));
}
__device__ __forceinline__ void mma16816(float* c, const uint32_t* a, const uint32_t* b) {
    asm volatile(
        "mma.sync.aligned.m16n8k16.row.col.f32.f16.f16.f32 "
        "{%0,%1,%2,%3}, {%4,%5,%6,%7}, {%8,%9}, {%0,%1,%2,%3};"
        : "+f"(c[0]), "+f"(c[1]), "+f"(c[2]), "+f"(c[3])
        : "r"(a[0]), "r"(a[1]), "r"(a[2]), "r"(a[3]), "r"(b[0]), "r"(b[1]));
}
__device__ __forceinline__ uint32_t h2u(__half2 h) {
    uint32_t u; __builtin_memcpy(&u, &h, 4); return u;
}

// ---------------- prep: W + X -> fp16 hi/lo + stat init ----------------
#define W_UNITS (N_TOT * HID / 8)          // 40960
#define W_BLOCKS (W_UNITS / 256)           // 160
#define X_BLOCKS (N_TOK * HID / 8 / 256)   // 16384

__global__ void prep_kernel(const float* __restrict__ X,
                            const float* __restrict__ RW, const float* __restrict__ W1) {
    if (blockIdx.x == 0 && threadIdx.x < NEXP) {
        g_load[threadIdx.x] = 0.0f;
        if (threadIdx.x == 0) g_ent = 0.0f;
    }
    const bool isW = blockIdx.x < W_BLOCKS;
    size_t u = isW ? ((size_t)blockIdx.x * 256 + threadIdx.x)
                   : ((size_t)(blockIdx.x - W_BLOCKS) * 256 + threadIdx.x);
    const float* src;
    __half *dhi, *dlo;
    if (isW) {
        size_t e = u * 8;
        int row = (int)(e >> 10);
        src = (row < NEXP) ? (RW + e) : (W1 + e - (size_t)NEXP * HID);
        dhi = g_whi + e; dlo = g_wlo + e;
    } else {
        src = X + u * 8;
        dhi = g_xhi + u * 8; dlo = g_xlo + u * 8;
    }
    float4 f0 = reinterpret_cast<const float4*>(src)[0];
    float4 f1 = reinterpret_cast<const float4*>(src)[1];
    __half2 h0 = __floats2half2_rn(f0.x, f0.y);
    __half2 h1 = __floats2half2_rn(f0.z, f0.w);
    __half2 h2 = __floats2half2_rn(f1.x, f1.y);
    __half2 h3 = __floats2half2_rn(f1.z, f1.w);
    float2 g0 = __half22float2(h0), g1 = __half22float2(h1);
    float2 g2 = __half22float2(h2), g3 = __half22float2(h3);
    __half2 l0 = __floats2half2_rn(f0.x - g0.x, f0.y - g0.y);
    __half2 l1 = __floats2half2_rn(f0.z - g1.x, f0.w - g1.y);
    __half2 l2 = __floats2half2_rn(f1.x - g2.x, f1.y - g2.y);
    __half2 l3 = __floats2half2_rn(f1.z - g3.x, f1.w - g3.y);
    *reinterpret_cast<uint4*>(dhi) = make_uint4(h2u(h0), h2u(h1), h2u(h2), h2u(h3));
    *reinterpret_cast<uint4*>(dlo) = make_uint4(h2u(l0), h2u(l1), h2u(l2), h2u(l3));
}

// ---------------- GEMM (2m x 8n warp grid) + fused router epilogue ----------------
__global__ void __launch_bounds__(THREADS, 1)
gemm_kernel(const float* __restrict__ B1, const float* __restrict__ W2,
            const float* __restrict__ B2,
            float* __restrict__ logits, float* __restrict__ sel, float* __restrict__ wts)
{
    extern __shared__ __align__(1024) char smem[];
    const uint32_t sbase = smem_u32(smem);
    const int tid = threadIdx.x;
    const int lane = tid & 31;
    const int wid = tid >> 5;
    const int wm = wid & 1;          // 2 m-groups * 64 rows
    const int wn = wid >> 1;         // 8 n-groups * 40 cols
    const int m0 = blockIdx.x * MT;

    float acc[4][5][4];
#pragma unroll
    for (int i = 0; i < 4; i++)
#pragma unroll
        for (int j = 0; j < 5; j++)
#pragma unroll
            for (int r = 0; r < 4; r++) acc[i][j][r] = 0.0f;

    // A ldsm addresses: 4 m16 tiles per warp
    uint32_t aOff[4], aXor[4];
#pragma unroll
    for (int mt = 0; mt < 4; mt++) {
        int row = wm * 64 + mt * 16 + (lane & 15);
        aOff[mt] = (uint32_t)row * 64;
        aXor[mt] = ((uint32_t)row * 8) & 0x30;
    }
    const uint32_t aKB = ((lane >> 4) & 1) * 16;

    // B ldsm addresses: 2 x4 pairs (nt 0-1, 2-3) + 1 x2 (nt 4)
    uint32_t bOff[3], bXor[3];
#pragma unroll
    for (int p = 0; p < 2; p++) {
        int n = wn * 40 + (p * 2 + ((lane >> 4) & 1)) * 8 + (lane & 7);
        bOff[p] = (uint32_t)n * 64;
        bXor[p] = ((uint32_t)n * 8) & 0x30;
    }
    {
        int n = wn * 40 + 32 + (lane & 7);   // x2: lanes 0-15 meaningful
        bOff[2] = (uint32_t)n * 64;
        bXor[2] = ((uint32_t)n * 8) & 0x30;
    }
    const uint32_t bKB = ((lane >> 3) & 1) * 16;

    // chunk issue: 3584 16B-units, 7 per thread
    auto issue = [&](int c) {
        if (c < NCHUNK) {
            const uint32_t sb = sbase + (uint32_t)(c & 3) * ST_BYTES;
            const size_t k0 = (size_t)c * KC;
#pragma unroll
            for (int it = 0; it < 7; it++) {
                int u = tid + it * THREADS;
                const __half* src;
                uint32_t dst;
                if (u < 1024) {
                    int v = u >= 512;
                    int j = v ? u - 512 : u;
                    int row = j >> 2, g = j & 3;
                    src = (v ? g_xlo : g_xhi) + (size_t)(m0 + row) * HID + k0 + g * 8;
                    dst = sb + v * A_LO_OFF +
                          ((uint32_t)row * 64 + (((uint32_t)g * 16) ^ (((uint32_t)row * 8) & 0x30)));
                } else {
                    int t = u - 1024;
                    int v = t >= 1280;
                    int j = v ? t - 1280 : t;
                    int n = j >> 2, g = j & 3;
                    src = (v ? g_wlo : g_whi) + (size_t)n * HID + k0 + g * 8;
                    dst = sb + (v ? B_LO_OFF : B_HI_OFF) +
                          ((uint32_t)n * 64 + (((uint32_t)g * 16) ^ (((uint32_t)n * 8) & 0x30)));
                }
                cp16(dst, src);
            }
        }
        asm volatile("cp.async.commit_group;");
    };

    issue(0); issue(1); issue(2);

    for (int c = 0; c < NCHUNK; c++) {
        asm volatile("cp.async.wait_group 2;");
        __syncthreads();
        issue(c + 3);

        const uint32_t sb = sbase + (uint32_t)(c & 3) * ST_BYTES;
#pragma unroll
        for (int ks = 0; ks < 2; ks++) {
            const uint32_t kb = ks * 32;
            uint32_t ah[4][4], bh[10], bl[10];
            // load ah + bh
#pragma unroll
            for (int mt = 0; mt < 4; mt++)
                ldsm4(ah[mt], sb + aOff[mt] + ((kb + aKB) ^ aXor[mt]));
#pragma unroll
            for (int p = 0; p < 2; p++)
                ldsm4(bh + p * 4, sb + B_HI_OFF + bOff[p] + ((kb + bKB) ^ bXor[p]));
            ldsm2(bh + 8, sb + B_HI_OFF + bOff[2] + ((kb + bKB) ^ bXor[2]));
            // pass 1: ah x bh
#pragma unroll
            for (int mt = 0; mt < 4; mt++) {
#pragma unroll
                for (int p = 0; p < 2; p++) {
                    mma16816(acc[mt][p * 2 + 0], ah[mt], bh + p * 4);
                    mma16816(acc[mt][p * 2 + 1], ah[mt], bh + p * 4 + 2);
                }
                mma16816(acc[mt][4], ah[mt], bh + 8);
            }
            // load bl
#pragma unroll
            for (int p = 0; p < 2; p++)
                ldsm4(bl + p * 4, sb + B_LO_OFF + bOff[p] + ((kb + bKB) ^ bXor[p]));
            ldsm2(bl + 8, sb + B_LO_OFF + bOff[2] + ((kb + bKB) ^ bXor[2]));
            // pass 3: ah x bl
#pragma unroll
            for (int mt = 0; mt < 4; mt++) {
#pragma unroll
                for (int p = 0; p < 2; p++) {
                    mma16816(acc[mt][p * 2 + 0], ah[mt], bl + p * 4);
                    mma16816(acc[mt][p * 2 + 1], ah[mt], bl + p * 4 + 2);
                }
                mma16816(acc[mt][4], ah[mt], bl + 8);
            }
            // load al into ah regs
#pragma unroll
            for (int mt = 0; mt < 4; mt++)
                ldsm4(ah[mt], sb + A_LO_OFF + aOff[mt] + ((kb + aKB) ^ aXor[mt]));
            // pass 2: al x bh
#pragma unroll
            for (int mt = 0; mt < 4; mt++) {
#pragma unroll
                for (int p = 0; p < 2; p++) {
                    mma16816(acc[mt][p * 2 + 0], ah[mt], bh + p * 4);
                    mma16816(acc[mt][p * 2 + 1], ah[mt], bh + p * 4 + 2);
                }
                mma16816(acc[mt][4], ah[mt], bh + 8);
            }
        }
    }

    // ---------------- fused epilogue ----------------
    float* s_log  = reinterpret_cast<float*>(smem);           // [128][68]
    float* s_u    = reinterpret_cast<float*>(smem + 34816);   // [128]
    float* s_load = s_u + 128;                                // [64]
    float* s_ent  = s_load + NEXP;

    __syncthreads();
    if (tid < MT)   s_u[tid] = B2[0];
    if (tid < NEXP) s_load[tid] = 0.0f;
    if (tid == 0)   *s_ent = 0.0f;
    __syncthreads();

    // phase A: logits -> smem, hidden -> u partials
#pragma unroll
    for (int mt = 0; mt < 4; mt++) {
        float u0 = 0.0f, u1 = 0.0f;
        const int row0 = wm * 64 + mt * 16 + (lane >> 2);
#pragma unroll
        for (int nt = 0; nt < 5; nt++) {
            const int nb = wn * 40 + nt * 8 + (lane & 3) * 2;
            const bool is_logit = (wn * 40 + nt * 8) < 64;   // frag-aligned boundary
#pragma unroll
            for (int r = 0; r < 4; r++) {
                const int n = nb + (r & 1);
                const float v = acc[mt][nt][r];
                if (is_logit) {
                    const int rl = row0 + ((r >= 2) ? 8 : 0);
                    s_log[rl * 68 + n] = v;
                } else {
                    const int h = n - 64;
                    const float hh = fmaxf(v + __ldg(B1 + h), 0.0f) * __ldg(W2 + h);
                    if (r < 2) u0 += hh; else u1 += hh;
                }
            }
        }
        u0 += __shfl_xor_sync(0xffffffffu, u0, 1);
        u0 += __shfl_xor_sync(0xffffffffu, u0, 2);
        u1 += __shfl_xor_sync(0xffffffffu, u1, 1);
        u1 += __shfl_xor_sync(0xffffffffu, u1, 2);
        if ((lane & 3) == 0 && wn >= 1) {
            atomicAdd(&s_u[row0], u0);
            atomicAdd(&s_u[row0 + 8], u1);
        }
    }
    __syncthreads();

    // phase B: logits -> global
#pragma unroll
    for (int it = 0; it < 4; it++) {
        int t = tid + it * THREADS;
        int r = t >> 4, c4 = t & 15;
        float4 v = *reinterpret_cast<const float4*>(s_log + r * 68 + c4 * 4);
        *reinterpret_cast<float4*>(logits + (size_t)(m0 + r) * NEXP + c4 * 4) = v;
    }

    // phase D: softmax stats, 4 lanes per token x 16 experts
    {
        const int t = tid >> 2, q = tid & 3;
        const float* row = s_log + t * 68 + q * 16;
        float xs[16];
        float mx = -INFINITY;
#pragma unroll
        for (int i = 0; i < 16; i++) { xs[i] = row[i]; mx = fmaxf(mx, xs[i]); }
        mx = fmaxf(mx, __shfl_xor_sync(0xffffffffu, mx, 1));
        mx = fmaxf(mx, __shfl_xor_sync(0xffffffffu, mx, 2));
        float se = 0.0f, sc = 0.0f;
#pragma unroll
        for (int i = 0; i < 16; i++) {
            float d = xs[i] - mx;
            float e = __expf(d);
            se += e;
            sc = fmaf(e, d, sc);
            xs[i] = e;
        }
        se += __shfl_xor_sync(0xffffffffu, se, 1);
        se += __shfl_xor_sync(0xffffffffu, se, 2);
        sc += __shfl_xor_sync(0xffffffffu, sc, 1);
        sc += __shfl_xor_sync(0xffffffffu, sc, 2);
        const float inv = 1.0f / se;
#pragma unroll
        for (int i = 0; i < 16; i++) {
            float p = xs[i] * inv;
            p += __shfl_xor_sync(0xffffffffu, p, 4);
            p += __shfl_xor_sync(0xffffffffu, p, 8);
            p += __shfl_xor_sync(0xffffffffu, p, 16);
            xs[i] = p;
        }
        if (lane < 4) {
#pragma unroll
            for (int i = 0; i < 16; i++) atomicAdd(&s_load[lane * 16 + i], xs[i]);
        }
        float ent = (q == 0) ? (__logf(se) - sc * inv) : 0.0f;
        ent += __shfl_xor_sync(0xffffffffu, ent, 1);
        ent += __shfl_xor_sync(0xffffffffu, ent, 2);
        ent += __shfl_xor_sync(0xffffffffu, ent, 4);
        ent += __shfl_xor_sync(0xffffffffu, ent, 8);
        ent += __shfl_xor_sync(0xffffffffu, ent, 16);
        if (lane == 0) atomicAdd(s_ent, ent);
    }
    __syncthreads();

    // phase C: top-k + weights; stats flush
    if (tid < MT) {
        const int m = m0 + tid;
        const float* row = s_log + tid * 68;

        float v0 = -INFINITY, v1 = -INFINITY, v2 = -INFINITY, v3 = -INFINITY;
        int i0 = 0, i1 = 0, i2 = 0, i3 = 0;
#pragma unroll
        for (int j = 0; j < NEXP; j++) {
            float x = row[j];
            if (x > v3) {
                if (x > v0)      { v3=v2;i3=i2; v2=v1;i2=i1; v1=v0;i1=i0; v0=x;i0=j; }
                else if (x > v1) { v3=v2;i3=i2; v2=v1;i2=i1; v1=x;i1=j; }
                else if (x > v2) { v3=v2;i3=i2; v2=x;i2=j; }
                else             { v3=x;i3=j; }
            }
        }
        float u = s_u[tid];
        float cplx = 1.0f / (1.0f + expf(-u));
        int kk = (cplx > 0.5f) ? 4 : 1;
        float e0 = 1.0f;
        float e1 = (kk > 1) ? expf(v1 - v0) : 0.0f;
        float e2 = (kk > 2) ? expf(v2 - v0) : 0.0f;
        float e3 = (kk > 3) ? expf(v3 - v0) : 0.0f;
        float wi = 1.0f / (e0 + e1 + e2 + e3);

        *reinterpret_cast<float4*>(sel + (size_t)m * 4) =
            make_float4((float)i0, (float)((kk > 1) ? i1 : 0),
                        (float)((kk > 2) ? i2 : 0), (float)((kk > 3) ? i3 : 0));
        *reinterpret_cast<float4*>(wts + (size_t)m * 4) =
            make_float4(e0 * wi, e1 * wi, e2 * wi, e3 * wi);
    } else if (tid < MT + NEXP) {
        atomicAdd(&g_load[tid - MT], s_load[tid - MT]);
    } else if (tid == MT + NEXP) {
        atomicAdd(&g_ent, *s_ent);
    }
}

// ---------------- finalize ----------------
__global__ void finalize_kernel(float* __restrict__ out_var, float* __restrict__ out_ent) {
    if (threadIdx.x == 0) {
        float xs[NEXP];
        float mean = 0.0f;
        for (int e = 0; e < NEXP; e++) { xs[e] = g_load[e] * (1.0f / N_TOK); mean += xs[e]; }
        mean *= (1.0f / NEXP);
        float var = 0.0f;
        for (int e = 0; e < NEXP; e++) { float d = xs[e] - mean; var += d * d; }
        out_var[0] = var * (1.0f / (NEXP - 1));
        out_ent[0] = g_ent * (1.0f / N_TOK);
    }
}

// ---------------- launch ----------------
extern "C" void kernel_launch(void* const* d_in, const int* in_sizes, int n_in,
                              void* d_out, int out_size) {
    const float* X  = (const float*)d_in[0];
    const float* RW = (const float*)d_in[1];
    const float* W1 = (const float*)d_in[2];
    const float* B1 = (const float*)d_in[3];
    const float* W2 = (const float*)d_in[4];
    const float* B2 = (const float*)d_in[5];

    float* out    = (float*)d_out;
    float* logits = out;
    float* sel    = logits + (size_t)N_TOK * NEXP;
    float* wts    = sel + (size_t)N_TOK * 4;
    float* ovar   = wts + (size_t)N_TOK * 4;
    float* oent   = ovar + 1;

    cudaFuncSetAttribute(gemm_kernel, cudaFuncAttributeMaxDynamicSharedMemorySize, SMEM_TOTAL);

    prep_kernel<<<W_BLOCKS + X_BLOCKS, 256>>>(X, RW, W1);
    gemm_kernel<<<N_TOK / MT, THREADS, SMEM_TOTAL>>>(B1, W2, B2, logits, sel, wts);
    finalize_kernel<<<1, 32>>>(ovar, oent);
}

// round 9
// speedup vs baseline: 1.0644x; 1.0644x over previous
#include <cuda_runtime.h>
#include <cuda_fp16.h>
#include <stdint.h>
#include <math.h>

#define N_TOK  32768
#define HID    1024
#define NEXP   64
#define H4     256
#define N_TOT  320          // 64 router + 256 hidden

#define MT      128         // M rows per CTA
#define KC      32          // K per chunk
#define NCHUNK  (HID / KC)  // 32
#define THREADS 512

// smem stage: A32 (128 rows x 160B pitch, 128B data) | B_HI 20480 | B_LO 20480
#define A_PITCH  160
#define B_HI_OFF 20480
#define B_LO_OFF 40960
#define ST_BYTES 61440
#define NSTAGE   3
#define SMEM_TOTAL (NSTAGE * ST_BYTES)   // 184320

// ---------------- device scratch (weights only now) ----------------
__device__ __align__(16) __half g_whi[N_TOT * HID];
__device__ __align__(16) __half g_wlo[N_TOT * HID];
__device__ float g_load[NEXP];
__device__ float g_ent;

__device__ __forceinline__ uint32_t smem_u32(const void* p) {
    uint32_t a;
    asm("{ .reg .u64 t; cvta.to.shared.u64 t, %1; cvt.u32.u64 %0, t; }" : "=r"(a) : "l"(p));
    return a;
}
__device__ __forceinline__ void cp16(uint32_t dst, const void* src) {
    asm volatile("cp.async.cg.shared.global [%0], [%1], 16;"
                 :: "r"(dst), "l"(__cvta_generic_to_global(src)));
}
__device__ __forceinline__ void ldsm4(uint32_t* r, uint32_t addr) {
    asm volatile("ldmatrix.sync.aligned.m8n8.x4.shared.b16 {%0,%1,%2,%3}, [%4];"
                 : "=r"(r[0]), "=r"(r[1]), "=r"(r[2]), "=r"(r[3]) : "r"(addr));
}
__device__ __forceinline__ void mma16816(float* c, const uint32_t* a, const uint32_t* b) {
    asm volatile(
        "mma.sync.aligned.m16n8k16.row.col.f32.f16.f16.f32 "
        "{%0,%1,%2,%3}, {%4,%5,%6,%7}, {%8,%9}, {%0,%1,%2,%3};"
        : "+f"(c[0]), "+f"(c[1]), "+f"(c[2]), "+f"(c[3])
        : "r"(a[0]), "r"(a[1]), "r"(a[2]), "r"(a[3]), "r"(b[0]), "r"(b[1]));
}
__device__ __forceinline__ uint32_t h2u(__half2 h) {
    uint32_t u; __builtin_memcpy(&u, &h, 4); return u;
}
// fp32 pair -> fp16 hi frag + fp16 residual frag
__device__ __forceinline__ void cvt_pair(float x, float y, uint32_t& hi, uint32_t& lo) {
    __half2 h = __floats2half2_rn(x, y);
    float2 g = __half22float2(h);
    __half2 l = __floats2half2_rn(x - g.x, y - g.y);
    hi = h2u(h); lo = h2u(l);
}
// shared load float2
__device__ __forceinline__ float2 lds64(const char* smem, uint32_t off) {
    return *reinterpret_cast<const float2*>(smem + off);
}

// ---------------- prep: weights only -> fp16 hi/lo + stat init ----------------
#define W_UNITS (N_TOT * HID / 8)   // 40960
#define W_BLOCKS (W_UNITS / 256)    // 160

__global__ void prep_w_kernel(const float* __restrict__ RW, const float* __restrict__ W1) {
    if (blockIdx.x == 0 && threadIdx.x < NEXP) {
        g_load[threadIdx.x] = 0.0f;
        if (threadIdx.x == 0) g_ent = 0.0f;
    }
    size_t u = (size_t)blockIdx.x * 256 + threadIdx.x;
    size_t e = u * 8;
    int row = (int)(e >> 10);
    const float* src = (row < NEXP) ? (RW + e) : (W1 + e - (size_t)NEXP * HID);
    float4 f0 = reinterpret_cast<const float4*>(src)[0];
    float4 f1 = reinterpret_cast<const float4*>(src)[1];
    uint32_t h0, l0, h1, l1, h2, l2, h3, l3;
    cvt_pair(f0.x, f0.y, h0, l0);
    cvt_pair(f0.z, f0.w, h1, l1);
    cvt_pair(f1.x, f1.y, h2, l2);
    cvt_pair(f1.z, f1.w, h3, l3);
    *reinterpret_cast<uint4*>(g_whi + e) = make_uint4(h0, h1, h2, h3);
    *reinterpret_cast<uint4*>(g_wlo + e) = make_uint4(l0, l1, l2, l3);
}

// ---------------- GEMM (A fp32->frags in regs) + fused router epilogue ----------------
__global__ void __launch_bounds__(THREADS, 1)
gemm_kernel(const float* __restrict__ X,
            const float* __restrict__ B1, const float* __restrict__ W2,
            const float* __restrict__ B2,
            float* __restrict__ logits, float* __restrict__ sel, float* __restrict__ wts)
{
    extern __shared__ __align__(1024) char smem[];
    const uint32_t sbase = smem_u32(smem);
    const int tid = threadIdx.x;
    const int lane = tid & 31;
    const int wid = tid >> 5;
    const int wm = wid & 3;          // 4 m-groups * 32 rows
    const int wn = wid >> 2;         // 4 n-groups * 80 cols
    const int m0 = blockIdx.x * MT;

    float acc[2][10][4];
#pragma unroll
    for (int i = 0; i < 2; i++)
#pragma unroll
        for (int j = 0; j < 10; j++)
#pragma unroll
            for (int r = 0; r < 4; r++) acc[i][j][r] = 0.0f;

    // A fp32 lane offsets (within stage): tile mt, positions (r,c),(r+8,c),(r,c+8),(r+8,c+8)
    uint32_t aL[2];
#pragma unroll
    for (int mt = 0; mt < 2; mt++) {
        int arow = wm * 32 + mt * 16 + (lane >> 2);
        aL[mt] = (uint32_t)arow * A_PITCH + (uint32_t)(lane & 3) * 8;
    }

    // B ldsm addresses (64B rows, SW64-style granule xor)
    uint32_t bOff[5], bXor[5];
#pragma unroll
    for (int p = 0; p < 5; p++) {
        int n = wn * 80 + (p * 2 + ((lane >> 4) & 1)) * 8 + (lane & 7);
        bOff[p] = (uint32_t)n * 64;
        bXor[p] = ((uint32_t)n * 8) & 0x30;
    }
    const uint32_t bKB = ((lane >> 3) & 1) * 16;

    // chunk issue: A fp32 1024 units + B 2560 units = 3584, 7 per thread
    auto issue = [&](int c) {
        if (c < NCHUNK) {
            const uint32_t sb = sbase + (uint32_t)(c % 3) * ST_BYTES;
            const size_t k0 = (size_t)c * KC;
#pragma unroll
            for (int it = 0; it < 7; it++) {
                int u = tid + it * THREADS;
                if (u < 1024) {
                    int r = u >> 3, g = u & 7;
                    const float* src = X + (size_t)(m0 + r) * HID + k0 + g * 4;
                    cp16(sb + (uint32_t)r * A_PITCH + (uint32_t)g * 16, src);
                } else {
                    int t = u - 1024;
                    int v = t >= 1280;
                    int j = v ? t - 1280 : t;
                    int n = j >> 2, g = j & 3;
                    const __half* src = (v ? g_wlo : g_whi) + (size_t)n * HID + k0 + g * 8;
                    cp16(sb + (v ? B_LO_OFF : B_HI_OFF) +
                         ((uint32_t)n * 64 + (((uint32_t)g * 16) ^ (((uint32_t)n * 8) & 0x30))),
                         src);
                }
            }
        }
        asm volatile("cp.async.commit_group;");
    };

    issue(0); issue(1);

    for (int c = 0; c < NCHUNK; c++) {
        asm volatile("cp.async.wait_group 1;");
        __syncthreads();
        issue(c + 2);

        const uint32_t stOff = (uint32_t)(c % 3) * ST_BYTES;
        const char* sA = smem + stOff;
        const uint32_t sb = sbase + stOff;
#pragma unroll
        for (int ks = 0; ks < 2; ks++) {
            const uint32_t kf = ks * 64;    // fp32 bytes for k16 step
            const uint32_t kb = ks * 32;    // f16 bytes for B
            uint32_t ah[2][4], al[2][4], bb[5][4];
            // assemble A frags (hi + lo) from fp32 smem
#pragma unroll
            for (int mt = 0; mt < 2; mt++) {
                uint32_t base = aL[mt] + kf;
                float2 f00 = lds64(sA, base);
                float2 f10 = lds64(sA, base + 8 * A_PITCH);
                float2 f01 = lds64(sA, base + 32);
                float2 f11 = lds64(sA, base + 8 * A_PITCH + 32);
                cvt_pair(f00.x, f00.y, ah[mt][0], al[mt][0]);
                cvt_pair(f10.x, f10.y, ah[mt][1], al[mt][1]);
                cvt_pair(f01.x, f01.y, ah[mt][2], al[mt][2]);
                cvt_pair(f11.x, f11.y, ah[mt][3], al[mt][3]);
            }
            // bh
#pragma unroll
            for (int p = 0; p < 5; p++)
                ldsm4(bb[p], sb + B_HI_OFF + bOff[p] + ((kb + bKB) ^ bXor[p]));
            // pass 1: ah x bh
#pragma unroll
            for (int mt = 0; mt < 2; mt++)
#pragma unroll
                for (int p = 0; p < 5; p++) {
                    mma16816(acc[mt][p * 2 + 0], ah[mt], &bb[p][0]);
                    mma16816(acc[mt][p * 2 + 1], ah[mt], &bb[p][2]);
                }
            // pass 2: al x bh
#pragma unroll
            for (int mt = 0; mt < 2; mt++)
#pragma unroll
                for (int p = 0; p < 5; p++) {
                    mma16816(acc[mt][p * 2 + 0], al[mt], &bb[p][0]);
                    mma16816(acc[mt][p * 2 + 1], al[mt], &bb[p][2]);
                }
            // bl (overwrite bb)
#pragma unroll
            for (int p = 0; p < 5; p++)
                ldsm4(bb[p], sb + B_LO_OFF + bOff[p] + ((kb + bKB) ^ bXor[p]));
            // pass 3: ah x bl
#pragma unroll
            for (int mt = 0; mt < 2; mt++)
#pragma unroll
                for (int p = 0; p < 5; p++) {
                    mma16816(acc[mt][p * 2 + 0], ah[mt], &bb[p][0]);
                    mma16816(acc[mt][p * 2 + 1], ah[mt], &bb[p][2]);
                }
        }
    }

    // ---------------- fused epilogue (R7) ----------------
    float* s_log  = reinterpret_cast<float*>(smem);           // [128][68]
    float* s_u    = reinterpret_cast<float*>(smem + 34816);   // [128]
    float* s_load = s_u + 128;                                // [64]
    float* s_ent  = s_load + NEXP;

    __syncthreads();
    if (tid < MT)   s_u[tid] = B2[0];
    if (tid < NEXP) s_load[tid] = 0.0f;
    if (tid == 0)   *s_ent = 0.0f;
    __syncthreads();

#pragma unroll
    for (int mt = 0; mt < 2; mt++) {
        float u0 = 0.0f, u1 = 0.0f;
        const int row0 = wm * 32 + mt * 16 + (lane >> 2);
#pragma unroll
        for (int nt = 0; nt < 10; nt++) {
            const int nb = wn * 80 + nt * 8 + (lane & 3) * 2;
            const bool is_logit = (wn == 0 && nt < 8);
#pragma unroll
            for (int r = 0; r < 4; r++) {
                const int n = nb + (r & 1);
                const float v = acc[mt][nt][r];
                if (is_logit) {
                    const int rl = row0 + ((r >= 2) ? 8 : 0);
                    s_log[rl * 68 + n] = v;
                } else {
                    const int h = n - 64;
                    const float hh = fmaxf(v + __ldg(B1 + h), 0.0f) * __ldg(W2 + h);
                    if (r < 2) u0 += hh; else u1 += hh;
                }
            }
        }
        u0 += __shfl_xor_sync(0xffffffffu, u0, 1);
        u0 += __shfl_xor_sync(0xffffffffu, u0, 2);
        u1 += __shfl_xor_sync(0xffffffffu, u1, 1);
        u1 += __shfl_xor_sync(0xffffffffu, u1, 2);
        if ((lane & 3) == 0) {
            atomicAdd(&s_u[row0], u0);
            atomicAdd(&s_u[row0 + 8], u1);
        }
    }
    __syncthreads();

    // logits -> global
#pragma unroll
    for (int it = 0; it < 4; it++) {
        int t = tid + it * THREADS;
        int r = t >> 4, c4 = t & 15;
        float4 v = *reinterpret_cast<const float4*>(s_log + r * 68 + c4 * 4);
        *reinterpret_cast<float4*>(logits + (size_t)(m0 + r) * NEXP + c4 * 4) = v;
    }

    // softmax stats: 4 lanes per token x 16 experts
    {
        const int t = tid >> 2, q = tid & 3;
        const float* row = s_log + t * 68 + q * 16;
        float xs[16];
        float mx = -INFINITY;
#pragma unroll
        for (int i = 0; i < 16; i++) { xs[i] = row[i]; mx = fmaxf(mx, xs[i]); }
        mx = fmaxf(mx, __shfl_xor_sync(0xffffffffu, mx, 1));
        mx = fmaxf(mx, __shfl_xor_sync(0xffffffffu, mx, 2));
        float se = 0.0f, sc = 0.0f;
#pragma unroll
        for (int i = 0; i < 16; i++) {
            float d = xs[i] - mx;
            float e = __expf(d);
            se += e;
            sc = fmaf(e, d, sc);
            xs[i] = e;
        }
        se += __shfl_xor_sync(0xffffffffu, se, 1);
        se += __shfl_xor_sync(0xffffffffu, se, 2);
        sc += __shfl_xor_sync(0xffffffffu, sc, 1);
        sc += __shfl_xor_sync(0xffffffffu, sc, 2);
        const float inv = 1.0f / se;
#pragma unroll
        for (int i = 0; i < 16; i++) {
            float p = xs[i] * inv;
            p += __shfl_xor_sync(0xffffffffu, p, 4);
            p += __shfl_xor_sync(0xffffffffu, p, 8);
            p += __shfl_xor_sync(0xffffffffu, p, 16);
            xs[i] = p;
        }
        if (lane < 4) {
#pragma unroll
            for (int i = 0; i < 16; i++) atomicAdd(&s_load[lane * 16 + i], xs[i]);
        }
        float ent = (q == 0) ? (__logf(se) - sc * inv) : 0.0f;
        ent += __shfl_xor_sync(0xffffffffu, ent, 1);
        ent += __shfl_xor_sync(0xffffffffu, ent, 2);
        ent += __shfl_xor_sync(0xffffffffu, ent, 4);
        ent += __shfl_xor_sync(0xffffffffu, ent, 8);
        ent += __shfl_xor_sync(0xffffffffu, ent, 16);
        if (lane == 0) atomicAdd(s_ent, ent);
    }
    __syncthreads();

    // top-k + weights; stats flush
    if (tid < MT) {
        const int m = m0 + tid;
        const float* row = s_log + tid * 68;

        float v0 = -INFINITY, v1 = -INFINITY, v2 = -INFINITY, v3 = -INFINITY;
        int i0 = 0, i1 = 0, i2 = 0, i3 = 0;
#pragma unroll
        for (int j = 0; j < NEXP; j++) {
            float x = row[j];
            if (x > v3) {
                if (x > v0)      { v3=v2;i3=i2; v2=v1;i2=i1; v1=v0;i1=i0; v0=x;i0=j; }
                else if (x > v1) { v3=v2;i3=i2; v2=v1;i2=i1; v1=x;i1=j; }
                else if (x > v2) { v3=v2;i3=i2; v2=x;i2=j; }
                else             { v3=x;i3=j; }
            }
        }
        float u = s_u[tid];
        float cplx = 1.0f / (1.0f + expf(-u));
        int kk = (cplx > 0.5f) ? 4 : 1;
        float e0 = 1.0f;
        float e1 = (kk > 1) ? expf(v1 - v0) : 0.0f;
        float e2 = (kk > 2) ? expf(v2 - v0) : 0.0f;
        float e3 = (kk > 3) ? expf(v3 - v0) : 0.0f;
        float wi = 1.0f / (e0 + e1 + e2 + e3);

        *reinterpret_cast<float4*>(sel + (size_t)m * 4) =
            make_float4((float)i0, (float)((kk > 1) ? i1 : 0),
                        (float)((kk > 2) ? i2 : 0), (float)((kk > 3) ? i3 : 0));
        *reinterpret_cast<float4*>(wts + (size_t)m * 4) =
            make_float4(e0 * wi, e1 * wi, e2 * wi, e3 * wi);
    } else if (tid < MT + NEXP) {
        atomicAdd(&g_load[tid - MT], s_load[tid - MT]);
    } else if (tid == MT + NEXP) {
        atomicAdd(&g_ent, *s_ent);
    }
}

// ---------------- finalize ----------------
__global__ void finalize_kernel(float* __restrict__ out_var, float* __restrict__ out_ent) {
    if (threadIdx.x == 0) {
        float xs[NEXP];
        float mean = 0.0f;
        for (int e = 0; e < NEXP; e++) { xs[e] = g_load[e] * (1.0f / N_TOK); mean += xs[e]; }
        mean *= (1.0f / NEXP);
        float var = 0.0f;
        for (int e = 0; e < NEXP; e++) { float d = xs[e] - mean; var += d * d; }
        out_var[0] = var * (1.0f / (NEXP - 1));
        out_ent[0] = g_ent * (1.0f / N_TOK);
    }
}

// ---------------- launch ----------------
extern "C" void kernel_launch(void* const* d_in, const int* in_sizes, int n_in,
                              void* d_out, int out_size) {
    const float* X  = (const float*)d_in[0];
    const float* RW = (const float*)d_in[1];
    const float* W1 = (const float*)d_in[2];
    const float* B1 = (const float*)d_in[3];
    const float* W2 = (const float*)d_in[4];
    const float* B2 = (const float*)d_in[5];

    float* out    = (float*)d_out;
    float* logits = out;
    float* sel    = logits + (size_t)N_TOK * NEXP;
    float* wts    = sel + (size_t)N_TOK * 4;
    float* ovar   = wts + (size_t)N_TOK * 4;
    float* oent   = ovar + 1;

    cudaFuncSetAttribute(gemm_kernel, cudaFuncAttributeMaxDynamicSharedMemorySize, SMEM_TOTAL);

    prep_w_kernel<<<W_BLOCKS, 256>>>(RW, W1);
    gemm_kernel<<<N_TOK / MT, THREADS, SMEM_TOTAL>>>(X, B1, W2, B2, logits, sel, wts);
    finalize_kernel<<<1, 32>>>(ovar, oent);
}